// round 10
// baseline (speedup 1.0000x reference)
#include <cuda_runtime.h>

static constexpr int AB    = 128;    // A*B
static constexpr int NROWS = 1024;   // N = M
static constexpr int KD    = 64;
static constexpr int RQ    = KD / 4; // float4 per row = 16
static constexpr int VCH   = 16;     // v-sum chunks per ab (64 rows each)
static constexpr int UCH   = 8;      // u/v gate chunks per ab (128 rows each)
static constexpr int NB_R  = 256, NB_U = 256, NB_V = 256;
static constexpr int RW    = 8,   UW   = 4,   VW   = 4;   // waves per role

// Partial column sums (fixed-order, deterministic)
__device__ float4 g_part_v[AB * VCH * RQ];
__device__ float4 g_part_u[AB * UCH * RQ];
// Per-ab completion counters (progress only; never affect numerics)
__device__ int g_vcnt[AB];
__device__ int g_ucnt[AB];

__global__ void reset_kernel() {
    if (threadIdx.x < AB) { g_vcnt[threadIdx.x] = 0; g_ucnt[threadIdx.x] = 0; }
}

__global__ void __launch_bounds__(256, 6)
fused_kernel(const float4* __restrict__ u,
             const float4* __restrict__ v,
             float4* __restrict__ out) {
    __shared__ float4 sred[16][16];
    const int blk = blockIdx.x;
    const int tid = threadIdx.x;

    if (blk < NB_R) {
        // ── Role R: v column-sum partials, 64-row chunks, ab-increasing ──
        const int q  = tid & 15;         // float4 column
        const int rg = tid >> 4;         // 0..15 row group
        for (int w = 0; w < RW; w++) {
            const int c   = w * NB_R + blk;      // 0..2047, ab-major
            const int ab  = c >> 4;
            const int sub = c & 15;
            const float4* __restrict__ base =
                v + ((size_t)ab * NROWS + sub * 64) * RQ;

            float4 s = make_float4(0.f, 0.f, 0.f, 0.f);
#pragma unroll
            for (int i = 0; i < 4; i++) {
                const float4 x = base[(size_t)(rg + i * 16) * RQ + q];
                s.x += x.x; s.y += x.y; s.z += x.z; s.w += x.w;
            }
            sred[rg][q] = s;
            __syncthreads();
#pragma unroll
            for (int stride = 8; stride > 0; stride >>= 1) {
                if (rg < stride) {
                    const float4 o = sred[rg + stride][q];
                    sred[rg][q].x += o.x; sred[rg][q].y += o.y;
                    sred[rg][q].z += o.z; sred[rg][q].w += o.w;
                }
                __syncthreads();
            }
            if (rg == 0) g_part_v[c * RQ + q] = sred[0][q];
            __syncthreads();                       // partial stored; smem reusable
            if (tid == 0) { __threadfence(); atomicAdd(&g_vcnt[ab], 1); }
        }
    } else if (blk < NB_R + NB_U) {
        // ── Role U: gate u with v_sum + produce u-sum partials ──
        const int ublk = blk - NB_R;
        const int warp = tid >> 5, lane = tid & 31;
        const int half = lane >> 4, q = lane & 15;
        for (int w = 0; w < UW; w++) {
            const int c   = w * NB_U + ublk;       // 0..1023, ab-major
            const int ab  = c >> 3;
            const int sub = c & 7;

            if (tid == 0) {
                while (atomicAdd(&g_vcnt[ab], 0) < VCH) __nanosleep(128);
                __threadfence();
            }
            __syncthreads();                       // acquire for whole block

            const float4* __restrict__ Pv = g_part_v + (size_t)ab * VCH * RQ + q;
            float4 sv = __ldg(Pv);
#pragma unroll
            for (int cc = 1; cc < VCH; cc++) {
                const float4 o = __ldg(Pv + cc * RQ);
                sv.x += o.x; sv.y += o.y; sv.z += o.z; sv.w += o.w;
            }

            const int    row0 = ab * NROWS + sub * 128 + warp * 16;
            const size_t base = (size_t)row0 * RQ + (size_t)half * RQ + q;

            float4 x[8];
#pragma unroll
            for (int j = 0; j < 8; j++) x[j] = __ldcs(u + base + (size_t)j * (2 * RQ));

            // u-sum partial: fold 8 slots, then the two 16-lane halves
            float4 cs = make_float4(0.f, 0.f, 0.f, 0.f);
#pragma unroll
            for (int j = 0; j < 8; j++) {
                cs.x += x[j].x; cs.y += x[j].y; cs.z += x[j].z; cs.w += x[j].w;
            }
            cs.x += __shfl_xor_sync(0xffffffffu, cs.x, 16);
            cs.y += __shfl_xor_sync(0xffffffffu, cs.y, 16);
            cs.z += __shfl_xor_sync(0xffffffffu, cs.z, 16);
            cs.w += __shfl_xor_sync(0xffffffffu, cs.w, 16);
            if (half == 0) sred[warp][q] = cs;     // first 8 rows of sred
            __syncthreads();
            if (tid < 16) {                        // serial 8-term fixed-order fold
                float4 a = sred[0][q];
#pragma unroll
                for (int wg = 1; wg < 8; wg++) {
                    const float4 o = sred[wg][q];
                    a.x += o.x; a.y += o.y; a.z += o.z; a.w += o.w;
                }
                g_part_u[c * RQ + q] = a;          // c == ab*8+sub
            }

            // gate: row dot vs sv, 4-level xor tree in the 16-lane segment
            float p[8];
#pragma unroll
            for (int j = 0; j < 8; j++)
                p[j] = fmaf(x[j].x, sv.x,
                        fmaf(x[j].y, sv.y,
                         fmaf(x[j].z, sv.z, x[j].w * sv.w)));
#pragma unroll
            for (int m = 8; m; m >>= 1)
#pragma unroll
                for (int j = 0; j < 8; j++)
                    p[j] += __shfl_xor_sync(0xffffffffu, p[j], m);
#pragma unroll
            for (int j = 0; j < 8; j++) {
                const float g = (p[j] > 0.f) ? 1.f : 0.f;
                __stcs(out + base + (size_t)j * (2 * RQ),
                       make_float4(x[j].x * g, x[j].y * g, x[j].z * g, x[j].w * g));
            }
            __syncthreads();                       // partial fold done; smem reusable
            if (tid == 0) { __threadfence(); atomicAdd(&g_ucnt[ab], 1); }
        }
    } else {
        // ── Role V: gate v with u_sum ──
        const int vblk = blk - NB_R - NB_U;
        const int warp = tid >> 5, lane = tid & 31;
        const int half = lane >> 4, q = lane & 15;
        float4* __restrict__ outv = out + (size_t)AB * NROWS * RQ;
        for (int w = 0; w < VW; w++) {
            const int c   = w * NB_V + vblk;
            const int ab  = c >> 3;
            const int sub = c & 7;

            if (tid == 0) {
                while (atomicAdd(&g_ucnt[ab], 0) < UCH) __nanosleep(128);
                __threadfence();
            }
            __syncthreads();

            const float4* __restrict__ Pu = g_part_u + (size_t)ab * UCH * RQ + q;
            float4 su = __ldg(Pu);
#pragma unroll
            for (int cc = 1; cc < UCH; cc++) {
                const float4 o = __ldg(Pu + cc * RQ);
                su.x += o.x; su.y += o.y; su.z += o.z; su.w += o.w;
            }

            const int    row0 = ab * NROWS + sub * 128 + warp * 16;
            const size_t base = (size_t)row0 * RQ + (size_t)half * RQ + q;

            float4 x[8];
#pragma unroll
            for (int j = 0; j < 8; j++) x[j] = __ldcs(v + base + (size_t)j * (2 * RQ));

            float p[8];
#pragma unroll
            for (int j = 0; j < 8; j++)
                p[j] = fmaf(x[j].x, su.x,
                        fmaf(x[j].y, su.y,
                         fmaf(x[j].z, su.z, x[j].w * su.w)));
#pragma unroll
            for (int m = 8; m; m >>= 1)
#pragma unroll
                for (int j = 0; j < 8; j++)
                    p[j] += __shfl_xor_sync(0xffffffffu, p[j], m);
#pragma unroll
            for (int j = 0; j < 8; j++) {
                const float g = (p[j] > 0.f) ? 1.f : 0.f;
                __stcs(outv + base + (size_t)j * (2 * RQ),
                       make_float4(x[j].x * g, x[j].y * g, x[j].z * g, x[j].w * g));
            }
        }
    }
}

// ---------------------------------------------------------------------------
extern "C" void kernel_launch(void* const* d_in, const int* in_sizes, int n_in,
                              void* d_out, int out_size) {
    const float4* u = (const float4*)d_in[0];
    const float4* v = (const float4*)d_in[1];

    reset_kernel<<<1, 128>>>();
    fused_kernel<<<NB_R + NB_U + NB_V, 256>>>(u, v, (float4*)d_out);
}